// round 2
// baseline (speedup 1.0000x reference)
#include <cuda_runtime.h>
#include <cstdint>
#include <math.h>

#define NB   16384
#define HID  1024
#define TH   3072
#define INP  1088
#define NEMB 100

// Scratch: h ping-pong buffers + precomputed embedding projection (includes b_ih).
__device__ float g_buf0[NB * HID];
__device__ float g_buf1[NB * HID];
__device__ float g_buf2[NB * HID];
__device__ float g_embproj[NEMB * TH];

// ---------------------------------------------------------------------------
// tf32 helpers
// ---------------------------------------------------------------------------
__device__ __forceinline__ uint32_t f2tf(float x) {
    uint32_t r;
    asm("cvt.rna.tf32.f32 %0, %1;" : "=r"(r) : "f"(x));
    return r;
}

__device__ __forceinline__ void mma8(float c[4], const uint32_t a[4], const uint32_t b[2]) {
    asm("mma.sync.aligned.m16n8k8.row.col.f32.tf32.tf32.f32 "
        "{%0,%1,%2,%3},{%4,%5,%6,%7},{%8,%9},{%0,%1,%2,%3};"
        : "+f"(c[0]), "+f"(c[1]), "+f"(c[2]), "+f"(c[3])
        : "r"(a[0]), "r"(a[1]), "r"(a[2]), "r"(a[3]), "r"(b[0]), "r"(b[1]));
}

struct Acc { float v[2][2][4]; };  // [m_tile][n_tile][c_reg]

// ---------------------------------------------------------------------------
// One GEMM pass: acc{R,Z,N} += A[iBase:iBase+128, k] * B_gate[jBase+g*1024 + n, bCol0+k]^T
// Block tile: BM=128, BN=32 (per gate), BK=32. 256 threads = 8 warps (4 M x 2 N).
// ---------------------------------------------------------------------------
__device__ __forceinline__ void gemm_pass(
    const float* __restrict__ A, int lda,
    const float* __restrict__ B, int ldb, int bCol0, int klen,
    uint32_t As[][36], uint32_t Bs[][32][36],
    Acc& aR, Acc& aZ, Acc& aN,
    int iBase, int jBase, int tid)
{
    const int lane = tid & 31;
    const int warp = tid >> 5;
    const int wm = warp & 3;   // 4 warps along M (32 rows each)
    const int wn = warp >> 2;  // 2 warps along N (16 cols each)

    for (int k0 = 0; k0 < klen; k0 += 32) {
        __syncthreads();
        // Load A tile (128 x 32), 1024 float4 -> 4 per thread, convert to tf32 bits.
        #pragma unroll
        for (int p = 0; p < 4; p++) {
            int q = tid + p * 256;
            int r = q >> 3;
            int c = (q & 7) * 4;
            float4 v = *(const float4*)&A[(size_t)(iBase + r) * lda + k0 + c];
            As[r][c + 0] = f2tf(v.x);
            As[r][c + 1] = f2tf(v.y);
            As[r][c + 2] = f2tf(v.z);
            As[r][c + 3] = f2tf(v.w);
        }
        // Load 3 gate B tiles (32 x 32 each), 256 float4 per gate -> 1 per thread.
        {
            int r = tid >> 3;
            int c = (tid & 7) * 4;
            #pragma unroll
            for (int g = 0; g < 3; g++) {
                float4 v = *(const float4*)&B[(size_t)(jBase + g * HID + r) * ldb + bCol0 + k0 + c];
                Bs[g][r][c + 0] = f2tf(v.x);
                Bs[g][r][c + 1] = f2tf(v.y);
                Bs[g][r][c + 2] = f2tf(v.z);
                Bs[g][r][c + 3] = f2tf(v.w);
            }
        }
        __syncthreads();

        #pragma unroll
        for (int ks = 0; ks < 4; ks++) {
            uint32_t af[2][4];
            #pragma unroll
            for (int mt = 0; mt < 2; mt++) {
                int r0 = wm * 32 + mt * 16 + (lane >> 2);
                int c0 = ks * 8 + (lane & 3);
                af[mt][0] = As[r0][c0];
                af[mt][1] = As[r0 + 8][c0];
                af[mt][2] = As[r0][c0 + 4];
                af[mt][3] = As[r0 + 8][c0 + 4];
            }
            #pragma unroll
            for (int g = 0; g < 3; g++) {
                Acc& acc = (g == 0) ? aR : (g == 1) ? aZ : aN;
                #pragma unroll
                for (int nt = 0; nt < 2; nt++) {
                    int bc = wn * 16 + nt * 8 + (lane >> 2);
                    int br = ks * 8 + (lane & 3);
                    uint32_t bf[2] = { Bs[g][bc][br], Bs[g][bc][br + 4] };
                    #pragma unroll
                    for (int mt = 0; mt < 2; mt++) mma8(acc.v[mt][nt], af[mt], bf);
                }
            }
        }
    }
}

// ---------------------------------------------------------------------------
// Fused GRU step: up to 3 GEMM passes + gate epilogue. Writes h_new directly.
//   GH     : gh = h @ W_hh^T (else gh = b_hh only; step 0)
//   GIMAIN : gi main part = giA @ W_ih[:, :1024]^T (steps 3,4)
//   EMB    : gi bias = embproj[id] gather (steps 0-2), else b_ih
// obs pass always runs: obs @ W_ih[:, obsWcol:obsWcol+64]^T
// ---------------------------------------------------------------------------
template <bool GH, bool GIMAIN, bool EMB>
__global__ void __launch_bounds__(256) gru_step_kernel(
    const float* __restrict__ hA,
    const float* __restrict__ giA,
    const float* __restrict__ obs,   // pre-offset by t*64; lda = 512
    int obsWcol,
    const float* __restrict__ Whh,
    const float* __restrict__ Wih,
    const float* __restrict__ b_ih,
    const float* __restrict__ b_hh,
    const int* __restrict__ ids,
    const float* __restrict__ hprev,
    float* __restrict__ hout)
{
    __shared__ uint32_t As[128][36];
    __shared__ uint32_t Bs[3][32][36];

    const int tid = threadIdx.x;
    const int iBase = blockIdx.y * 128;
    const int jBase = blockIdx.x * 32;

    Acc aR = {}, aZ = {}, aNi = {}, aNh = {};

    if (GH)
        gemm_pass(hA, HID, Whh, HID, 0, HID, As, Bs, aR, aZ, aNh, iBase, jBase, tid);
    if (GIMAIN)
        gemm_pass(giA, HID, Wih, INP, 0, HID, As, Bs, aR, aZ, aNi, iBase, jBase, tid);
    // obs part (K = 64)
    gemm_pass(obs, 512, Wih, INP, obsWcol, 64, As, Bs, aR, aZ, aNi, iBase, jBase, tid);

    // Epilogue: gates
    const int lane = tid & 31;
    const int warp = tid >> 5;
    const int wm = warp & 3;
    const int wn = warp >> 2;

    #pragma unroll
    for (int mt = 0; mt < 2; mt++)
        #pragma unroll
        for (int nt = 0; nt < 2; nt++)
            #pragma unroll
            for (int c = 0; c < 4; c++) {
                int row = wm * 32 + mt * 16 + (lane >> 2) + ((c >= 2) ? 8 : 0);
                int col = wn * 16 + nt * 8 + (lane & 3) * 2 + (c & 1);
                int i = iBase + row;
                int jg = jBase + col;
                float gr, gz, gn;
                if (EMB) {
                    const float* ep = g_embproj + (size_t)ids[i] * TH;
                    gr = ep[jg]; gz = ep[jg + 1024]; gn = ep[jg + 2048];
                } else {
                    gr = b_ih[jg]; gz = b_ih[jg + 1024]; gn = b_ih[jg + 2048];
                }
                float rp = aR.v[mt][nt][c] + gr + b_hh[jg];
                float zp = aZ.v[mt][nt][c] + gz + b_hh[jg + 1024];
                float ni = aNi.v[mt][nt][c] + gn;
                float nh = aNh.v[mt][nt][c] + b_hh[jg + 2048];
                float r = 1.f / (1.f + expf(-rp));
                float z = 1.f / (1.f + expf(-zp));
                float n = tanhf(ni + r * nh);
                float hp = GH ? hprev[(size_t)i * HID + jg] : 0.f;
                hout[(size_t)i * HID + jg] = (1.f - z) * n + z * hp;
            }
}

// ---------------------------------------------------------------------------
// embproj[e][j] = b_ih[j] + sum_k emb[e][k] * W_ih[j][64+k]
// grid (3072/128, 10 groups of 10 embeddings), block 128.
// ---------------------------------------------------------------------------
__global__ void __launch_bounds__(128) embproj_kernel(
    const float* __restrict__ emb,
    const float* __restrict__ Wih,
    const float* __restrict__ b_ih)
{
    __shared__ float se[10][1024];
    const int tid = threadIdx.x;
    const int eg = blockIdx.y;               // embedding group, 10 per group
    const int j = blockIdx.x * 128 + tid;    // 0..3071

    for (int q = tid; q < 10 * 256; q += 128) {
        int e = q >> 8;
        int k = (q & 255) * 4;
        float4 v = *(const float4*)&emb[(size_t)(eg * 10 + e) * 1024 + k];
        se[e][k] = v.x; se[e][k + 1] = v.y; se[e][k + 2] = v.z; se[e][k + 3] = v.w;
    }
    __syncthreads();

    float acc[10];
    #pragma unroll
    for (int e = 0; e < 10; e++) acc[e] = 0.f;

    const float* w = Wih + (size_t)j * INP + 64;
    for (int k = 0; k < 1024; k += 4) {
        float4 wv = *(const float4*)&w[k];
        #pragma unroll
        for (int e = 0; e < 10; e++)
            acc[e] += wv.x * se[e][k] + wv.y * se[e][k + 1] +
                      wv.z * se[e][k + 2] + wv.w * se[e][k + 3];
    }
    float b = b_ih[j];
    #pragma unroll
    for (int e = 0; e < 10; e++)
        g_embproj[(size_t)(eg * 10 + e) * TH + j] = b + acc[e];
}

// ---------------------------------------------------------------------------
extern "C" void kernel_launch(void* const* d_in, const int* in_sizes, int n_in,
                              void* d_out, int out_size)
{
    const float* obs  = (const float*)d_in[0];  // (16384, 8, 64)
    const int*   ids  = (const int*)  d_in[1];  // (16384,)
    const float* emb  = (const float*)d_in[2];  // (100, 1024)
    const float* Wih  = (const float*)d_in[3];  // (3072, 1088)
    const float* Whh  = (const float*)d_in[4];  // (3072, 1024)
    const float* b_ih = (const float*)d_in[5];  // (3072,)
    const float* b_hh = (const float*)d_in[6];  // (3072,)
    float* out = (float*)d_out;                 // (1, 16384, 1024)

    void *p0, *p1, *p2;
    cudaGetSymbolAddress(&p0, g_buf0);
    cudaGetSymbolAddress(&p1, g_buf1);
    cudaGetSymbolAddress(&p2, g_buf2);
    float* b0 = (float*)p0;
    float* b1 = (float*)p1;
    float* b2 = (float*)p2;

    embproj_kernel<<<dim3(TH / 128, 10), 128>>>(emb, Wih, b_ih);

    dim3 gs(HID / 32, NB / 128);  // (32, 128): x = hidden cols (L2 reuse of A band)

    // step 0: h=0 -> gh=b_hh; gi = obs0 @ Wih[:,:64]^T + embproj[id]
    gru_step_kernel<false, false, true><<<gs, 256>>>(
        nullptr, nullptr, obs + 0 * 64, 0, Whh, Wih, b_ih, b_hh, ids, nullptr, b0);
    // step 1: gh = h0 @ Whh^T; gi = obs1 @ Wih[:,:64]^T + embproj[id]
    gru_step_kernel<true, false, true><<<gs, 256>>>(
        b0, nullptr, obs + 1 * 64, 0, Whh, Wih, b_ih, b_hh, ids, b0, b1);
    // step 2: obs2
    gru_step_kernel<true, false, true><<<gs, 256>>>(
        b1, nullptr, obs + 2 * 64, 0, Whh, Wih, b_ih, b_hh, ids, b1, b2);
    // step 3: gi = [out0, obs1]: main = h0 @ Wih[:, :1024]^T, obs cols 1024:1088
    gru_step_kernel<true, true, false><<<gs, 256>>>(
        b2, b0, obs + 1 * 64, 1024, Whh, Wih, b_ih, b_hh, ids, b2, b1);
    // step 4: gi = [h3, obs2]
    gru_step_kernel<true, true, false><<<gs, 256>>>(
        b1, b1, obs + 2 * 64, 1024, Whh, Wih, b_ih, b_hh, ids, b1, out);
}

// round 5
// speedup vs baseline: 1.5911x; 1.5911x over previous
#include <cuda_runtime.h>
#include <cuda_fp16.h>
#include <cstdint>
#include <math.h>

#define NBUOY 16384
#define HID   1024
#define TH    3072
#define INP   1088
#define NEMB  100

// Tiles
#define BM  128
#define BNG 64     // per-gate N tile (3 gates -> 192 output cols per CTA)
#define BK  64

// SMEM: 3 stages x (A 16KB + 3x B 8KB) = 3 x 40960
#define STAGE_BYTES 40960
#define SMEM_BYTES  (3 * STAGE_BYTES)

// ---------------------------------------------------------------------------
// Scratch (device globals)
// ---------------------------------------------------------------------------
__device__ __half g_wih_h[TH * INP];
__device__ __half g_whh_h[TH * HID];
__device__ __half g_obs_h[NBUOY * 512];
__device__ __half g_h0[NBUOY * HID];
__device__ __half g_h1[NBUOY * HID];
__device__ __half g_h2[NBUOY * HID];
__device__ __half g_h3[NBUOY * HID];
__device__ float  g_f0[NBUOY * HID];
__device__ float  g_f1[NBUOY * HID];
__device__ float  g_embproj[NEMB * TH];

// ---------------------------------------------------------------------------
// helpers
// ---------------------------------------------------------------------------
__device__ __forceinline__ uint32_t smem_u32(const void* p) {
    uint32_t a;
    asm("{ .reg .u64 t; cvta.to.shared.u64 t, %1; cvt.u32.u64 %0, t; }" : "=r"(a) : "l"(p));
    return a;
}
#define SWZ(b) ((b) ^ (((b) >> 3) & 0x70))

#define CP_ASYNC16(dst, src) \
    asm volatile("cp.async.cg.shared.global [%0], [%1], 16;" :: "r"(dst), "l"(src) : "memory")

__device__ __forceinline__ void ldsm_x4(uint32_t r[4], uint32_t addr) {
    asm volatile("ldmatrix.sync.aligned.m8n8.x4.shared.b16 {%0,%1,%2,%3}, [%4];"
                 : "=r"(r[0]), "=r"(r[1]), "=r"(r[2]), "=r"(r[3]) : "r"(addr));
}

__device__ __forceinline__ void mma16816(float c[4], const uint32_t a[4], const uint32_t b[2]) {
    asm volatile("mma.sync.aligned.m16n8k16.row.col.f32.f16.f16.f32 "
                 "{%0,%1,%2,%3},{%4,%5,%6,%7},{%8,%9},{%0,%1,%2,%3};"
                 : "+f"(c[0]), "+f"(c[1]), "+f"(c[2]), "+f"(c[3])
                 : "r"(a[0]), "r"(a[1]), "r"(a[2]), "r"(a[3]), "r"(b[0]), "r"(b[1]));
}

// ---------------------------------------------------------------------------
// chunk loader: issues cp.async for one K-chunk (A 128x64 fp16 + 3 B gate tiles 64x64)
// ---------------------------------------------------------------------------
template <bool GH, bool GI>
__device__ __forceinline__ void load_chunk(
    int c, uint32_t sbase,
    const __half* __restrict__ hA, const __half* __restrict__ giA,
    const __half* __restrict__ obs, int obsWcol,
    const __half* __restrict__ Whh, const __half* __restrict__ Wih,
    int iBase, int jBase, int tid)
{
    constexpr int NCGH = GH ? 16 : 0;
    constexpr int NCGI = GI ? 16 : 0;
    const __half* Ap; int lda, acol; const __half* Bp; int ldb, bcol;
    if (GH && c < NCGH) {
        Ap = hA;  lda = 1024; acol = c * 64;
        Bp = Whh; ldb = 1024; bcol = c * 64;
    } else if (GI && c < NCGH + NCGI) {
        int k = c - NCGH;
        Ap = giA; lda = 1024; acol = k * 64;
        Bp = Wih; ldb = 1088; bcol = k * 64;
    } else {
        Ap = obs; lda = 512;  acol = 0;
        Bp = Wih; ldb = 1088; bcol = obsWcol;
    }
    uint32_t sb = sbase + (c % 3) * STAGE_BYTES;
    // A: 128 rows x 128B = 1024 chunks of 16B
    #pragma unroll
    for (int p = 0; p < 4; ++p) {
        int q = tid + (p << 8);
        int row = q >> 3, c8 = q & 7;
        const __half* src = Ap + (size_t)(iBase + row) * lda + acol + c8 * 8;
        CP_ASYNC16(sb + SWZ(row * 128 + c8 * 16), src);
    }
    // B: 3 gates x 64 rows x 128B = 1536 chunks
    #pragma unroll
    for (int p = 0; p < 6; ++p) {
        int q = tid + (p << 8);
        int g = q >> 9, rr = (q >> 3) & 63, c8 = q & 7;
        const __half* src = Bp + (size_t)(g * 1024 + jBase + rr) * ldb + bcol + c8 * 8;
        CP_ASYNC16(sb + 16384 + g * 8192 + SWZ(rr * 128 + c8 * 16), src);
    }
    asm volatile("cp.async.commit_group;" ::: "memory");
}

// ---------------------------------------------------------------------------
// Fused GRU step (fp16 mma.sync, cp.async pipeline)
// ---------------------------------------------------------------------------
template <bool GH, bool GI, bool EMB, bool WR>
__global__ void __launch_bounds__(256, 1) gru_fp16_kernel(
    const __half* __restrict__ hA,
    const __half* __restrict__ giA,
    const __half* __restrict__ obs,   // pre-offset by t*64, lda=512
    int obsWcol,
    const __half* __restrict__ Whh,
    const __half* __restrict__ Wih,
    const float* __restrict__ b_ih,
    const float* __restrict__ b_hh,
    const int* __restrict__ ids,
    const float* __restrict__ hprev,
    float* __restrict__ hout,
    __half* __restrict__ hrnd)
{
    extern __shared__ __align__(1024) unsigned char smem[];
    constexpr int NCGH = GH ? 16 : 0;
    constexpr int NCGI = GI ? 16 : 0;
    constexpr int NC = NCGH + NCGI + 1;

    const int tid  = threadIdx.x;
    const int lane = tid & 31;
    const int warp = tid >> 5;
    const int wm   = warp & 3;   // M: 4 warps x 32 rows
    const int wn   = warp >> 2;  // N: 2 warps x 32 cols (per gate)
    const int iBase = blockIdx.y * BM;
    const int jBase = blockIdx.x * BNG;
    const uint32_t sbase = smem_u32(smem);

    // ldmatrix lane geometry
    const int a_row = wm * 32 + ((lane >> 3) & 1) * 8 + (lane & 7);
    const int a_kx  = ((lane >> 4) & 1) * 16;
    const uint32_t a_xor = (uint32_t)((a_row & 7) << 4);
    const int b_row = wn * 32 + ((lane >> 4) & 1) * 8 + (lane & 7);
    const int b_kx  = ((lane >> 3) & 1) * 16;
    const uint32_t b_xor = (uint32_t)((b_row & 7) << 4);

    float aR[2][4][4] = {}, aZ[2][4][4] = {}, aNi[2][4][4] = {}, aNh[2][4][4] = {};

    int loaded = 0;
    #pragma unroll
    for (; loaded < 2 && loaded < NC; ++loaded)
        load_chunk<GH, GI>(loaded, sbase, hA, giA, obs, obsWcol, Whh, Wih, iBase, jBase, tid);

    #pragma unroll 1
    for (int c = 0; c < NC; ++c) {
        if (loaded == c + 2) asm volatile("cp.async.wait_group 1;" ::: "memory");
        else                 asm volatile("cp.async.wait_group 0;" ::: "memory");
        __syncthreads();
        if (loaded < NC) {
            load_chunk<GH, GI>(loaded, sbase, hA, giA, obs, obsWcol, Whh, Wih, iBase, jBase, tid);
            ++loaded;
        }
        const bool isGH = GH && (c < NCGH);
        float (*aN)[4][4] = isGH ? aNh : aNi;
        uint32_t sb = sbase + (c % 3) * STAGE_BYTES;

        #pragma unroll
        for (int k16 = 0; k16 < 4; ++k16) {
            uint32_t a[2][4];
            #pragma unroll
            for (int mt = 0; mt < 2; ++mt)
                ldsm_x4(a[mt], sb + (uint32_t)((a_row + mt * 16) * 128) +
                               ((uint32_t)(k16 * 32 + a_kx) ^ a_xor));
            #pragma unroll
            for (int g = 0; g < 3; ++g) {
                uint32_t bb[4][2];
                uint32_t gb = sb + 16384 + g * 8192;
                #pragma unroll
                for (int np = 0; np < 2; ++np) {
                    uint32_t r[4];
                    ldsm_x4(r, gb + (uint32_t)((b_row + np * 16) * 128) +
                               ((uint32_t)(k16 * 32 + b_kx) ^ b_xor));
                    bb[np * 2 + 0][0] = r[0]; bb[np * 2 + 0][1] = r[1];
                    bb[np * 2 + 1][0] = r[2]; bb[np * 2 + 1][1] = r[3];
                }
                float (*acc)[4][4] = (g == 0) ? aR : (g == 1) ? aZ : aN;
                #pragma unroll
                for (int mt = 0; mt < 2; ++mt)
                    #pragma unroll
                    for (int nt = 0; nt < 4; ++nt)
                        mma16816(acc[mt][nt], a[mt], bb[nt]);
            }
        }
    }

    // -----------------------------------------------------------------------
    // Epilogue: gates + blend, direct coalesced stores
    // -----------------------------------------------------------------------
    const int row0 = iBase + wm * 32 + (lane >> 2);
    const int col0 = jBase + wn * 32 + (lane & 3) * 2;
    #pragma unroll
    for (int mt = 0; mt < 2; ++mt) {
        #pragma unroll
        for (int rh = 0; rh < 2; ++rh) {
            const int i = row0 + mt * 16 + rh * 8;
            const float* ep = EMB ? (g_embproj + (size_t)ids[i] * TH) : b_ih;
            #pragma unroll
            for (int nt = 0; nt < 4; ++nt) {
                const int jg = col0 + nt * 8;
                float2 gr  = *(const float2*)&ep[jg];
                float2 gz  = *(const float2*)&ep[jg + 1024];
                float2 gn  = *(const float2*)&ep[jg + 2048];
                float2 bhr = *(const float2*)&b_hh[jg];
                float2 bhz = *(const float2*)&b_hh[jg + 1024];
                float2 bhn = *(const float2*)&b_hh[jg + 2048];
                float2 hp = GH ? *(const float2*)&hprev[(size_t)i * 1024 + jg]
                               : make_float2(0.f, 0.f);
                float2 hv;
                #pragma unroll
                for (int e = 0; e < 2; ++e) {
                    float rp = aR[mt][nt][rh * 2 + e] + (e ? gr.y : gr.x) + (e ? bhr.y : bhr.x);
                    float zp = aZ[mt][nt][rh * 2 + e] + (e ? gz.y : gz.x) + (e ? bhz.y : bhz.x);
                    float ni = aNi[mt][nt][rh * 2 + e] + (e ? gn.y : gn.x);
                    float nh = (GH ? aNh[mt][nt][rh * 2 + e] : 0.f) + (e ? bhn.y : bhn.x);
                    float r = 1.f / (1.f + expf(-rp));
                    float z = 1.f / (1.f + expf(-zp));
                    float n = tanhf(ni + r * nh);
                    float h = (1.f - z) * n + z * (e ? hp.y : hp.x);
                    if (e) hv.y = h; else hv.x = h;
                }
                *(float2*)&hout[(size_t)i * 1024 + jg] = hv;
                if (WR)
                    *(__half2*)&hrnd[(size_t)i * 1024 + jg] = __floats2half2_rn(hv.x, hv.y);
            }
        }
    }
}

// ---------------------------------------------------------------------------
// Prep: fp32 -> fp16 conversion (n divisible by 4)
// ---------------------------------------------------------------------------
__global__ void __launch_bounds__(256) f2h_kernel(
    const float4* __restrict__ src, __half2* __restrict__ dst, int n4)
{
    int i = blockIdx.x * 256 + threadIdx.x;
    if (i < n4) {
        float4 v = src[i];
        dst[i * 2 + 0] = __floats2half2_rn(v.x, v.y);
        dst[i * 2 + 1] = __floats2half2_rn(v.z, v.w);
    }
}

// ---------------------------------------------------------------------------
// Prep: embproj[e][j] = b_ih[j] + sum_k emb[e][k] * W_ih[j][64+k]   (fp32)
// ---------------------------------------------------------------------------
__global__ void __launch_bounds__(128) embproj_kernel(
    const float* __restrict__ emb,
    const float* __restrict__ Wih,
    const float* __restrict__ b_ih)
{
    __shared__ float se[10][1024];
    const int tid = threadIdx.x;
    const int eg = blockIdx.y;
    const int j = blockIdx.x * 128 + tid;

    for (int q = tid; q < 10 * 256; q += 128) {
        int e = q >> 8;
        int k = (q & 255) * 4;
        float4 v = *(const float4*)&emb[(size_t)(eg * 10 + e) * 1024 + k];
        se[e][k] = v.x; se[e][k + 1] = v.y; se[e][k + 2] = v.z; se[e][k + 3] = v.w;
    }
    __syncthreads();

    float acc[10];
    #pragma unroll
    for (int e = 0; e < 10; ++e) acc[e] = 0.f;
    const float* w = Wih + (size_t)j * INP + 64;
    for (int k = 0; k < 1024; k += 4) {
        float4 wv = *(const float4*)&w[k];
        #pragma unroll
        for (int e = 0; e < 10; ++e)
            acc[e] += wv.x * se[e][k] + wv.y * se[e][k + 1] +
                      wv.z * se[e][k + 2] + wv.w * se[e][k + 3];
    }
    float b = b_ih[j];
    #pragma unroll
    for (int e = 0; e < 10; ++e)
        g_embproj[(size_t)(eg * 10 + e) * TH + j] = b + acc[e];
}

// ---------------------------------------------------------------------------
extern "C" void kernel_launch(void* const* d_in, const int* in_sizes, int n_in,
                              void* d_out, int out_size)
{
    const float* obs  = (const float*)d_in[0];  // (16384, 8, 64)
    const int*   ids  = (const int*)  d_in[1];  // (16384,)
    const float* emb  = (const float*)d_in[2];  // (100, 1024)
    const float* Wih  = (const float*)d_in[3];  // (3072, 1088)
    const float* Whh  = (const float*)d_in[4];  // (3072, 1024)
    const float* b_ih = (const float*)d_in[5];  // (3072,)
    const float* b_hh = (const float*)d_in[6];  // (3072,)
    float* out = (float*)d_out;                 // (1, 16384, 1024)

    void *pwi, *pwh, *pob, *ph0, *ph1, *ph2, *ph3, *pf0, *pf1;
    cudaGetSymbolAddress(&pwi, g_wih_h);
    cudaGetSymbolAddress(&pwh, g_whh_h);
    cudaGetSymbolAddress(&pob, g_obs_h);
    cudaGetSymbolAddress(&ph0, g_h0);
    cudaGetSymbolAddress(&ph1, g_h1);
    cudaGetSymbolAddress(&ph2, g_h2);
    cudaGetSymbolAddress(&ph3, g_h3);
    cudaGetSymbolAddress(&pf0, g_f0);
    cudaGetSymbolAddress(&pf1, g_f1);
    __half *wih_h = (__half*)pwi, *whh_h = (__half*)pwh, *obs_h = (__half*)pob;
    __half *h0 = (__half*)ph0, *h1 = (__half*)ph1, *h2 = (__half*)ph2, *h3 = (__half*)ph3;
    float *f0 = (float*)pf0, *f1 = (float*)pf1;

    cudaFuncSetAttribute(gru_fp16_kernel<false, false, true,  true >, cudaFuncAttributeMaxDynamicSharedMemorySize, SMEM_BYTES);
    cudaFuncSetAttribute(gru_fp16_kernel<true,  false, true,  true >, cudaFuncAttributeMaxDynamicSharedMemorySize, SMEM_BYTES);
    cudaFuncSetAttribute(gru_fp16_kernel<true,  true,  false, true >, cudaFuncAttributeMaxDynamicSharedMemorySize, SMEM_BYTES);
    cudaFuncSetAttribute(gru_fp16_kernel<true,  true,  false, false>, cudaFuncAttributeMaxDynamicSharedMemorySize, SMEM_BYTES);

    // Prep
    f2h_kernel<<<(TH * INP / 4 + 255) / 256, 256>>>((const float4*)Wih, (__half2*)wih_h, TH * INP / 4);
    f2h_kernel<<<(TH * HID / 4 + 255) / 256, 256>>>((const float4*)Whh, (__half2*)whh_h, TH * HID / 4);
    f2h_kernel<<<(NBUOY * 512 / 4 + 255) / 256, 256>>>((const float4*)obs, (__half2*)obs_h, NBUOY * 512 / 4);
    embproj_kernel<<<dim3(TH / 128, 10), 128>>>(emb, Wih, b_ih);

    dim3 gs(HID / BNG, NBUOY / BM);  // (16, 128)

    // step 0: h=0; gi = obs0 @ Wih[:, :64]^T + embproj[id]
    gru_fp16_kernel<false, false, true, true><<<gs, 256, SMEM_BYTES>>>(
        nullptr, nullptr, obs_h + 0, 0, whh_h, wih_h, b_ih, b_hh, ids, nullptr, f0, h0);
    // step 1
    gru_fp16_kernel<true, false, true, true><<<gs, 256, SMEM_BYTES>>>(
        h0, nullptr, obs_h + 64, 0, whh_h, wih_h, b_ih, b_hh, ids, f0, f1, h1);
    // step 2
    gru_fp16_kernel<true, false, true, true><<<gs, 256, SMEM_BYTES>>>(
        h1, nullptr, obs_h + 128, 0, whh_h, wih_h, b_ih, b_hh, ids, f1, f0, h2);
    // step 3: x = [h0, obs1]
    gru_fp16_kernel<true, true, false, true><<<gs, 256, SMEM_BYTES>>>(
        h2, h0, obs_h + 64, 1024, whh_h, wih_h, b_ih, b_hh, ids, f0, f1, h3);
    // step 4: x = [h3, obs2] -> final output
    gru_fp16_kernel<true, true, false, false><<<gs, 256, SMEM_BYTES>>>(
        h3, h3, obs_h + 128, 1024, whh_h, wih_h, b_ih, b_hh, ids, f1, out, nullptr);
}

// round 6
// speedup vs baseline: 1.9257x; 1.2103x over previous
#include <cuda_runtime.h>
#include <cuda_fp16.h>
#include <cstdint>
#include <math.h>

#define NBUOY 16384
#define HID   1024
#define TH    3072
#define INP   1088
#define NEMB  100

// Tiles
#define BM  128
#define BNG 32     // per-gate N tile (3 gates -> 96 output cols per CTA)
#define BK  64

// SMEM: 3 stages x (A 16KB + 3x B 4KB) = 3 x 28672 = 86016
#define STAGE_BYTES 28672
#define SMEM_BYTES  (3 * STAGE_BYTES)

// ---------------------------------------------------------------------------
// Scratch (device globals)
// ---------------------------------------------------------------------------
__device__ __half g_wih_h[TH * INP];
__device__ __half g_whh_h[TH * HID];
__device__ __half g_obs_h[NBUOY * 512];
__device__ __half g_h0[NBUOY * HID];
__device__ __half g_h1[NBUOY * HID];
__device__ __half g_h2[NBUOY * HID];
__device__ __half g_h3[NBUOY * HID];
__device__ float  g_f0[NBUOY * HID];
__device__ float  g_f1[NBUOY * HID];
__device__ float  g_embproj[NEMB * TH];

// ---------------------------------------------------------------------------
// helpers
// ---------------------------------------------------------------------------
__device__ __forceinline__ uint32_t smem_u32(const void* p) {
    uint32_t a;
    asm("{ .reg .u64 t; cvta.to.shared.u64 t, %1; cvt.u32.u64 %0, t; }" : "=r"(a) : "l"(p));
    return a;
}
#define SWZ(b) ((b) ^ (((b) >> 3) & 0x70))

#define CP_ASYNC16(dst, src) \
    asm volatile("cp.async.cg.shared.global [%0], [%1], 16;" :: "r"(dst), "l"(src) : "memory")

__device__ __forceinline__ void ldsm_x4(uint32_t r[4], uint32_t addr) {
    asm volatile("ldmatrix.sync.aligned.m8n8.x4.shared.b16 {%0,%1,%2,%3}, [%4];"
                 : "=r"(r[0]), "=r"(r[1]), "=r"(r[2]), "=r"(r[3]) : "r"(addr));
}

__device__ __forceinline__ void mma16816(float c[4], const uint32_t a[4], const uint32_t b[2]) {
    asm volatile("mma.sync.aligned.m16n8k16.row.col.f32.f16.f16.f32 "
                 "{%0,%1,%2,%3},{%4,%5,%6,%7},{%8,%9},{%0,%1,%2,%3};"
                 : "+f"(c[0]), "+f"(c[1]), "+f"(c[2]), "+f"(c[3])
                 : "r"(a[0]), "r"(a[1]), "r"(a[2]), "r"(a[3]), "r"(b[0]), "r"(b[1]));
}

// ---------------------------------------------------------------------------
// chunk loader: one K-chunk (A 128x64 fp16 + 3 B gate tiles 32x64)
// ---------------------------------------------------------------------------
template <bool GH, bool GI>
__device__ __forceinline__ void load_chunk(
    int c, uint32_t sbase,
    const __half* __restrict__ hA, const __half* __restrict__ giA,
    const __half* __restrict__ obs, int obsWcol,
    const __half* __restrict__ Whh, const __half* __restrict__ Wih,
    int iBase, int jBase, int tid)
{
    constexpr int NCGH = GH ? 16 : 0;
    constexpr int NCGI = GI ? 16 : 0;
    const __half* Ap; int lda, acol; const __half* Bp; int ldb, bcol;
    if (GH && c < NCGH) {
        Ap = hA;  lda = 1024; acol = c * 64;
        Bp = Whh; ldb = 1024; bcol = c * 64;
    } else if (GI && c < NCGH + NCGI) {
        int k = c - NCGH;
        Ap = giA; lda = 1024; acol = k * 64;
        Bp = Wih; ldb = 1088; bcol = k * 64;
    } else {
        Ap = obs; lda = 512;  acol = 0;
        Bp = Wih; ldb = 1088; bcol = obsWcol;
    }
    uint32_t sb = sbase + (c % 3) * STAGE_BYTES;
    // A: 128 rows x 128B = 1024 chunks of 16B
    #pragma unroll
    for (int p = 0; p < 4; ++p) {
        int q = tid + (p << 8);
        int row = q >> 3, c8 = q & 7;
        const __half* src = Ap + (size_t)(iBase + row) * lda + acol + c8 * 8;
        CP_ASYNC16(sb + SWZ(row * 128 + c8 * 16), src);
    }
    // B: 3 gates x 32 rows x 128B = 768 chunks
    #pragma unroll
    for (int p = 0; p < 3; ++p) {
        int q = tid + (p << 8);
        int g = q >> 8, rr = (q >> 3) & 31, c8 = q & 7;
        const __half* src = Bp + (size_t)(g * 1024 + jBase + rr) * ldb + bcol + c8 * 8;
        CP_ASYNC16(sb + 16384 + g * 4096 + SWZ(rr * 128 + c8 * 16), src);
    }
    asm volatile("cp.async.commit_group;" ::: "memory");
}

// ---------------------------------------------------------------------------
// Fused GRU step (fp16 mma.sync, cp.async pipeline, 2 CTAs/SM)
// ---------------------------------------------------------------------------
template <bool GH, bool GI, bool EMB, bool WR>
__global__ void __launch_bounds__(256, 2) gru_fp16_kernel(
    const __half* __restrict__ hA,
    const __half* __restrict__ giA,
    const __half* __restrict__ obs,   // pre-offset by t*64, lda=512
    int obsWcol,
    const __half* __restrict__ Whh,
    const __half* __restrict__ Wih,
    const float* __restrict__ b_ih,
    const float* __restrict__ b_hh,
    const int* __restrict__ ids,
    const float* __restrict__ hprev,
    float* __restrict__ hout,
    __half* __restrict__ hrnd)
{
    extern __shared__ __align__(1024) unsigned char smem[];
    constexpr int NCGH = GH ? 16 : 0;
    constexpr int NCGI = GI ? 16 : 0;
    constexpr int NC = NCGH + NCGI + 1;

    const int tid  = threadIdx.x;
    const int lane = tid & 31;
    const int warp = tid >> 5;
    const int wm   = warp & 3;   // M: 4 warps x 32 rows
    const int wn   = warp >> 2;  // N: 2 warps x 16 cols (per gate)
    const int iBase = blockIdx.y * BM;
    const int jBase = blockIdx.x * BNG;
    const uint32_t sbase = smem_u32(smem);

    // ldmatrix lane geometry
    const int a_row = wm * 32 + ((lane >> 3) & 1) * 8 + (lane & 7);
    const int a_kx  = ((lane >> 4) & 1) * 16;
    const uint32_t a_xor = (uint32_t)((a_row & 7) << 4);
    const int b_row = wn * 16 + ((lane >> 4) & 1) * 8 + (lane & 7);
    const int b_kx  = ((lane >> 3) & 1) * 16;
    const uint32_t b_xor = (uint32_t)((b_row & 7) << 4);

    float aR[2][2][4] = {}, aZ[2][2][4] = {}, aNi[2][2][4] = {}, aNh[2][2][4] = {};

    int loaded = 0;
    #pragma unroll
    for (; loaded < 2 && loaded < NC; ++loaded)
        load_chunk<GH, GI>(loaded, sbase, hA, giA, obs, obsWcol, Whh, Wih, iBase, jBase, tid);

    #pragma unroll 1
    for (int c = 0; c < NC; ++c) {
        if (loaded == c + 2) asm volatile("cp.async.wait_group 1;" ::: "memory");
        else                 asm volatile("cp.async.wait_group 0;" ::: "memory");
        __syncthreads();
        if (loaded < NC) {
            load_chunk<GH, GI>(loaded, sbase, hA, giA, obs, obsWcol, Whh, Wih, iBase, jBase, tid);
            ++loaded;
        }
        const bool isGH = GH && (c < NCGH);
        uint32_t sb = sbase + (c % 3) * STAGE_BYTES;

        #pragma unroll
        for (int k16 = 0; k16 < 4; ++k16) {
            uint32_t a[2][4];
            #pragma unroll
            for (int mt = 0; mt < 2; ++mt)
                ldsm_x4(a[mt], sb + (uint32_t)((a_row + mt * 16) * 128) +
                               ((uint32_t)(k16 * 32 + a_kx) ^ a_xor));
            #pragma unroll
            for (int g = 0; g < 3; ++g) {
                uint32_t r[4];
                ldsm_x4(r, sb + 16384 + g * 4096 + (uint32_t)(b_row * 128) +
                           ((uint32_t)(k16 * 32 + b_kx) ^ b_xor));
                uint32_t bb0[2] = { r[0], r[1] };
                uint32_t bb1[2] = { r[2], r[3] };
                float (*acc)[2][4] = (g == 0) ? aR : (g == 1) ? aZ : (isGH ? aNh : aNi);
                #pragma unroll
                for (int mt = 0; mt < 2; ++mt) {
                    mma16816(acc[mt][0], a[mt], bb0);
                    mma16816(acc[mt][1], a[mt], bb1);
                }
            }
        }
    }

    // -----------------------------------------------------------------------
    // Epilogue: gates + blend, direct coalesced stores
    // -----------------------------------------------------------------------
    const int row0 = iBase + wm * 32 + (lane >> 2);
    const int col0 = jBase + wn * 16 + (lane & 3) * 2;
    #pragma unroll
    for (int mt = 0; mt < 2; ++mt) {
        #pragma unroll
        for (int rh = 0; rh < 2; ++rh) {
            const int i = row0 + mt * 16 + rh * 8;
            const float* ep = EMB ? (g_embproj + (size_t)ids[i] * TH) : b_ih;
            #pragma unroll
            for (int nt = 0; nt < 2; ++nt) {
                const int jg = col0 + nt * 8;
                float2 gr  = *(const float2*)&ep[jg];
                float2 gz  = *(const float2*)&ep[jg + 1024];
                float2 gn  = *(const float2*)&ep[jg + 2048];
                float2 bhr = *(const float2*)&b_hh[jg];
                float2 bhz = *(const float2*)&b_hh[jg + 1024];
                float2 bhn = *(const float2*)&b_hh[jg + 2048];
                float2 hp = GH ? *(const float2*)&hprev[(size_t)i * 1024 + jg]
                               : make_float2(0.f, 0.f);
                float2 hv;
                #pragma unroll
                for (int e = 0; e < 2; ++e) {
                    float rp = aR[mt][nt][rh * 2 + e] + (e ? gr.y : gr.x) + (e ? bhr.y : bhr.x);
                    float zp = aZ[mt][nt][rh * 2 + e] + (e ? gz.y : gz.x) + (e ? bhz.y : bhz.x);
                    float ni = aNi[mt][nt][rh * 2 + e] + (e ? gn.y : gn.x);
                    float nh = (GH ? aNh[mt][nt][rh * 2 + e] : 0.f) + (e ? bhn.y : bhn.x);
                    float r = 1.f / (1.f + expf(-rp));
                    float z = 1.f / (1.f + expf(-zp));
                    float n = tanhf(ni + r * nh);
                    float h = (1.f - z) * n + z * (e ? hp.y : hp.x);
                    if (e) hv.y = h; else hv.x = h;
                }
                *(float2*)&hout[(size_t)i * 1024 + jg] = hv;
                if (WR)
                    *(__half2*)&hrnd[(size_t)i * 1024 + jg] = __floats2half2_rn(hv.x, hv.y);
            }
        }
    }
}

// ---------------------------------------------------------------------------
// Prep: fp32 -> fp16 conversion (n divisible by 4)
// ---------------------------------------------------------------------------
__global__ void __launch_bounds__(256) f2h_kernel(
    const float4* __restrict__ src, __half2* __restrict__ dst, int n4)
{
    int i = blockIdx.x * 256 + threadIdx.x;
    if (i < n4) {
        float4 v = src[i];
        dst[i * 2 + 0] = __floats2half2_rn(v.x, v.y);
        dst[i * 2 + 1] = __floats2half2_rn(v.z, v.w);
    }
}

// ---------------------------------------------------------------------------
// Prep: embproj[e][j] = b_ih[j] + sum_k emb[e][k] * W_ih[j][64+k]   (fp32)
// 5 embeddings per block, 480 blocks.
// ---------------------------------------------------------------------------
__global__ void __launch_bounds__(128) embproj_kernel(
    const float* __restrict__ emb,
    const float* __restrict__ Wih,
    const float* __restrict__ b_ih)
{
    __shared__ float se[5][1024];
    const int tid = threadIdx.x;
    const int eg = blockIdx.y;               // 20 groups of 5 embeddings
    const int j = blockIdx.x * 128 + tid;

    for (int q = tid; q < 5 * 256; q += 128) {
        int e = q >> 8;
        int k = (q & 255) * 4;
        float4 v = *(const float4*)&emb[(size_t)(eg * 5 + e) * 1024 + k];
        se[e][k] = v.x; se[e][k + 1] = v.y; se[e][k + 2] = v.z; se[e][k + 3] = v.w;
    }
    __syncthreads();

    float acc[5];
    #pragma unroll
    for (int e = 0; e < 5; ++e) acc[e] = 0.f;
    const float* w = Wih + (size_t)j * INP + 64;
    for (int k = 0; k < 1024; k += 4) {
        float4 wv = *(const float4*)&w[k];
        #pragma unroll
        for (int e = 0; e < 5; ++e)
            acc[e] += wv.x * se[e][k] + wv.y * se[e][k + 1] +
                      wv.z * se[e][k + 2] + wv.w * se[e][k + 3];
    }
    float b = b_ih[j];
    #pragma unroll
    for (int e = 0; e < 5; ++e)
        g_embproj[(size_t)(eg * 5 + e) * TH + j] = b + acc[e];
}

// ---------------------------------------------------------------------------
extern "C" void kernel_launch(void* const* d_in, const int* in_sizes, int n_in,
                              void* d_out, int out_size)
{
    const float* obs  = (const float*)d_in[0];  // (16384, 8, 64)
    const int*   ids  = (const int*)  d_in[1];  // (16384,)
    const float* emb  = (const float*)d_in[2];  // (100, 1024)
    const float* Wih  = (const float*)d_in[3];  // (3072, 1088)
    const float* Whh  = (const float*)d_in[4];  // (3072, 1024)
    const float* b_ih = (const float*)d_in[5];  // (3072,)
    const float* b_hh = (const float*)d_in[6];  // (3072,)
    float* out = (float*)d_out;                 // (1, 16384, 1024)

    void *pwi, *pwh, *pob, *ph0, *ph1, *ph2, *ph3, *pf0, *pf1;
    cudaGetSymbolAddress(&pwi, g_wih_h);
    cudaGetSymbolAddress(&pwh, g_whh_h);
    cudaGetSymbolAddress(&pob, g_obs_h);
    cudaGetSymbolAddress(&ph0, g_h0);
    cudaGetSymbolAddress(&ph1, g_h1);
    cudaGetSymbolAddress(&ph2, g_h2);
    cudaGetSymbolAddress(&ph3, g_h3);
    cudaGetSymbolAddress(&pf0, g_f0);
    cudaGetSymbolAddress(&pf1, g_f1);
    __half *wih_h = (__half*)pwi, *whh_h = (__half*)pwh, *obs_h = (__half*)pob;
    __half *h0 = (__half*)ph0, *h1 = (__half*)ph1, *h2 = (__half*)ph2, *h3 = (__half*)ph3;
    float *f0 = (float*)pf0, *f1 = (float*)pf1;

    cudaFuncSetAttribute(gru_fp16_kernel<false, false, true,  true >, cudaFuncAttributeMaxDynamicSharedMemorySize, SMEM_BYTES);
    cudaFuncSetAttribute(gru_fp16_kernel<true,  false, true,  true >, cudaFuncAttributeMaxDynamicSharedMemorySize, SMEM_BYTES);
    cudaFuncSetAttribute(gru_fp16_kernel<true,  true,  false, true >, cudaFuncAttributeMaxDynamicSharedMemorySize, SMEM_BYTES);
    cudaFuncSetAttribute(gru_fp16_kernel<true,  true,  false, false>, cudaFuncAttributeMaxDynamicSharedMemorySize, SMEM_BYTES);

    // Prep
    f2h_kernel<<<(TH * INP / 4 + 255) / 256, 256>>>((const float4*)Wih, (__half2*)wih_h, TH * INP / 4);
    f2h_kernel<<<(TH * HID / 4 + 255) / 256, 256>>>((const float4*)Whh, (__half2*)whh_h, TH * HID / 4);
    f2h_kernel<<<(NBUOY * 512 / 4 + 255) / 256, 256>>>((const float4*)obs, (__half2*)obs_h, NBUOY * 512 / 4);
    embproj_kernel<<<dim3(TH / 128, 20), 128>>>(emb, Wih, b_ih);

    dim3 gs(HID / BNG, NBUOY / BM);  // (32, 128)

    // step 0: h=0; gi = obs0 @ Wih[:, :64]^T + embproj[id]
    gru_fp16_kernel<false, false, true, true><<<gs, 256, SMEM_BYTES>>>(
        nullptr, nullptr, obs_h + 0, 0, whh_h, wih_h, b_ih, b_hh, ids, nullptr, f0, h0);
    // step 1
    gru_fp16_kernel<true, false, true, true><<<gs, 256, SMEM_BYTES>>>(
        h0, nullptr, obs_h + 64, 0, whh_h, wih_h, b_ih, b_hh, ids, f0, f1, h1);
    // step 2
    gru_fp16_kernel<true, false, true, true><<<gs, 256, SMEM_BYTES>>>(
        h1, nullptr, obs_h + 128, 0, whh_h, wih_h, b_ih, b_hh, ids, f1, f0, h2);
    // step 3: x = [h0, obs1]
    gru_fp16_kernel<true, true, false, true><<<gs, 256, SMEM_BYTES>>>(
        h2, h0, obs_h + 64, 1024, whh_h, wih_h, b_ih, b_hh, ids, f0, f1, h3);
    // step 4: x = [h3, obs2] -> final output
    gru_fp16_kernel<true, true, false, false><<<gs, 256, SMEM_BYTES>>>(
        h3, h3, obs_h + 128, 1024, whh_h, wih_h, b_ih, b_hh, ids, f1, out, nullptr);
}